// round 8
// baseline (speedup 1.0000x reference)
#include <cuda_runtime.h>

// MixedActivation: cols with (col % 6) < 3 -> x*x ; else PReLU with slope
// prelu_a[(col % 6) - 3]. x is [1000000, 48] fp32, contiguous.
//
// R7 resubmit (previous run died to container infra failure, no measurement):
// same geometry as R6 (best: 53.66us kernel, exact grid 15625, zero
// predicates) but DEFAULT cache policy instead of .cs streaming hints.
// Hypothesis: evict-first stores force eager R/W interleave at the memory
// controller; default policy lets L2 (126MB) batch dirty writebacks into
// longer write bursts, reducing bus-turnaround loss (the identified ceiling:
// ~6.1 TB/s across every supply shape tested in R2/R4/R5/R6).
//
// Phase logic: float4 index i covers cols 4i..4i+3; (4i) mod 6 depends only
// on r = i % 3: r=0 -> mods {0,1,2,3}, r=1 -> {4,5,0,1}, r=2 -> {2,3,4,5}.

#define UNROLL 3
#define TPB 256

__global__ void __launch_bounds__(TPB)
mixed_act_kernel(const float4* __restrict__ in,
                 const float* __restrict__ pa,
                 float4* __restrict__ out) {
    const int base = blockIdx.x * (TPB * UNROLL) + threadIdx.x;

    const float a0 = __ldg(pa + 0);
    const float a1 = __ldg(pa + 1);
    const float a2 = __ldg(pa + 2);

    // Front-batch all loads: 3 independent LDG.128 in flight per thread.
    float4 v[UNROLL];
#pragma unroll
    for (int k = 0; k < UNROLL; k++)
        v[k] = in[base + k * TPB];          // default cache policy

#pragma unroll
    for (int k = 0; k < UNROLL; k++) {
        const int i = base + k * TPB;
        int r = i % 3;       // phase of this float4 within the 6-col pattern
        int m0 = r * 4;      // (col % 12) of component 0; reduce mod 6 per c

        float x[4] = {v[k].x, v[k].y, v[k].z, v[k].w};
        float o[4];
#pragma unroll
        for (int c = 0; c < 4; c++) {
            int m = m0 + c;
            if (m >= 6) m -= 6;                   // m = col % 6 (0..5)
            float a = (m == 3) ? a0 : ((m == 4) ? a1 : a2);
            float sq = x[c] * x[c];
            float pr = fmaxf(x[c], 0.0f) + a * fminf(x[c], 0.0f);
            o[c] = (m < 3) ? sq : pr;             // predicated select
        }
        out[i] = make_float4(o[0], o[1], o[2], o[3]);  // default policy store
    }
}

extern "C" void kernel_launch(void* const* d_in, const int* in_sizes, int n_in,
                              void* d_out, int out_size) {
    const float* x  = (const float*)d_in[0];
    const float* pa = (const float*)d_in[1];
    float* out = (float*)d_out;

    int n4 = out_size / 4;                   // 12,000,000 float4s
    int blocks = n4 / (TPB * UNROLL);        // exactly 15625
    mixed_act_kernel<<<blocks, TPB>>>((const float4*)x, pa, (float4*)out);
}